// round 11
// baseline (speedup 1.0000x reference)
#include <cuda_runtime.h>
#include <cuda_bf16.h>
#include <math.h>

// Problem constants (fixed by setup_inputs)
#define BB   8
#define CC   256
#define HH   128
#define WW   128
#define HWP  (HH * WW)        // 16384 pixels per image
#define CO   21
#define NSEG (BB * CO)        // 168
#define EPSN 1e-12f

// ---------------- scratch (device globals; no allocation allowed) ----------
__device__ unsigned char g_pseudo[BB * HWP];        // 128 KB
__device__ float g_sum_cur[NSEG * CC];              // 172 KB
__device__ float g_sum_ref[NSEG * CC];
__device__ int   g_cnt[NSEG];
__device__ float g_pT_cur[CC * NSEG];               // transposed prototypes [C][NSEG]
__device__ float g_pT_ref[CC * NSEG];
__device__ float g_vm[NSEG];
__device__ float g_sq;

// ---------------- kernel 0: zero accumulators ------------------------------
__global__ void k_zero() {
    int t = threadIdx.x;
    if (t < NSEG) g_cnt[t] = 0;
    if (t == 0)   g_sq = 0.0f;
}

// ---------------- kernel 1: pseudo labels + per-seg counts -----------------
// grid (HWP/256, BB), block 256
__global__ void __launch_bounds__(256) k_pseudo(const float* __restrict__ outputs_old,
                                                const int*   __restrict__ labels,
                                                const int*   __restrict__ num_old) {
    __shared__ int s_cnt[CO];
    const int b   = blockIdx.y;
    const int p   = blockIdx.x * 256 + threadIdx.x;
    const int no  = num_old ? num_old[0] : 16;     // uniform; fallback if scalar not materialized
    if (threadIdx.x < CO) s_cnt[threadIdx.x] = 0;
    __syncthreads();

    const float* base = outputs_old + (size_t)b * CO * HWP + p;
    float best = base[0];
    int   bi   = 0;
#pragma unroll
    for (int ch = 1; ch < CO; ch++) {
        float v = base[(size_t)ch * HWP];
        if (v > best) { best = v; bi = ch; }   // strict > keeps first occurrence (jnp.argmax)
    }
    const int lab = labels[b * HWP + p];
    const int cls = (lab < no) ? bi : 0;
    g_pseudo[b * HWP + p] = (unsigned char)cls;
    atomicAdd(&s_cnt[cls], 1);
    __syncthreads();
    if (threadIdx.x < CO)
        atomicAdd(&g_cnt[b * CO + threadIdx.x], s_cnt[threadIdx.x]);
}

// ---------------- kernel 2: fused segment sums (dominant kernel) -----------
// grid (CC, BB), block 256. One block per (b,c).
// Each thread owns smem column tid: addr = cls*256 + tid -> bank = tid%32,
// conflict-free read-modify-write, no atomics in the pixel loop.
__global__ void __launch_bounds__(256) k_segsum(const float* __restrict__ feat,
                                                const float* __restrict__ feat_old) {
    __shared__ float s_cur[CO * 256];   // 21504 B
    __shared__ float s_ref[CO * 256];   // 21504 B
    const int tid = threadIdx.x;
    const int c   = blockIdx.x;
    const int b   = blockIdx.y;

#pragma unroll
    for (int r = 0; r < CO; r++) { s_cur[r * 256 + tid] = 0.0f; s_ref[r * 256 + tid] = 0.0f; }
    __syncthreads();

    const float4* __restrict__ f4 = (const float4*)(feat     + ((size_t)(b * CC + c)) * HWP);
    const float4* __restrict__ g4 = (const float4*)(feat_old + ((size_t)(b * CC + c)) * HWP);
    const uchar4* __restrict__ p4 = (const uchar4*)(g_pseudo + (size_t)b * HWP);

#pragma unroll
    for (int k = 0; k < HWP / 4 / 256; k++) {     // 16 iterations, fully unrolled
        const int idx = k * 256 + tid;            // float4 index
        const float4 fv = f4[idx];
        const float4 gv = g4[idx];
        const uchar4 pv = p4[idx];
        s_cur[pv.x * 256 + tid] += fv.x;
        s_cur[pv.y * 256 + tid] += fv.y;
        s_cur[pv.z * 256 + tid] += fv.z;
        s_cur[pv.w * 256 + tid] += fv.w;
        s_ref[pv.x * 256 + tid] += gv.x;
        s_ref[pv.y * 256 + tid] += gv.y;
        s_ref[pv.z * 256 + tid] += gv.z;
        s_ref[pv.w * 256 + tid] += gv.w;
    }
    __syncthreads();

    // reduce 2*CO rows of 256; each (b,c) owns unique output -> plain stores
    const int warp = tid >> 5, lane = tid & 31;
    for (int row = warp; row < 2 * CO; row += 8) {
        const float* sarr = (row < CO) ? s_cur : s_ref;
        const int r = (row < CO) ? row : row - CO;
        float v = 0.0f;
#pragma unroll
        for (int k = 0; k < 8; k++) v += sarr[r * 256 + lane + k * 32];
#pragma unroll
        for (int off = 16; off; off >>= 1) v += __shfl_down_sync(0xffffffffu, v, off);
        if (lane == 0) {
            float* dst = (row < CO) ? g_sum_cur : g_sum_ref;
            dst[(size_t)(b * CO + r) * CC + c] = v;
        }
    }
}

// ---------------- kernel 3: mean + L2 normalize, store transposed ----------
// grid NSEG, block 256 (tid == channel)
__global__ void __launch_bounds__(256) k_norm() {
    __shared__ float red[2][8];
    __shared__ float s_inv[2];
    const int i   = blockIdx.x;
    const int tid = threadIdx.x;
    const int warp = tid >> 5, lane = tid & 31;

    const float denom = fmaxf((float)g_cnt[i], 1.0f);
    const float mc = g_sum_cur[(size_t)i * CC + tid] / denom;
    const float mr = g_sum_ref[(size_t)i * CC + tid] / denom;

    float sc = mc * mc, sr = mr * mr;
#pragma unroll
    for (int off = 16; off; off >>= 1) {
        sc += __shfl_down_sync(0xffffffffu, sc, off);
        sr += __shfl_down_sync(0xffffffffu, sr, off);
    }
    if (lane == 0) { red[0][warp] = sc; red[1][warp] = sr; }
    __syncthreads();
    if (warp == 0) {
        float a  = (lane < 8) ? red[0][lane] : 0.0f;
        float b2 = (lane < 8) ? red[1][lane] : 0.0f;
#pragma unroll
        for (int off = 4; off; off >>= 1) {
            a  += __shfl_down_sync(0xffffffffu, a,  off);
            b2 += __shfl_down_sync(0xffffffffu, b2, off);
        }
        if (lane == 0) {
            s_inv[0] = 1.0f / fmaxf(sqrtf(a),  EPSN);
            s_inv[1] = 1.0f / fmaxf(sqrtf(b2), EPSN);
        }
    }
    __syncthreads();
    g_pT_cur[(size_t)tid * NSEG + i] = mc * s_inv[0];
    g_pT_ref[(size_t)tid * NSEG + i] = mr * s_inv[1];
    if (tid == 0)
        g_vm[i] = (g_cnt[i] > 0 && (i % CO) != 0) ? 1.0f : 0.0f;
}

// ---------------- kernel 4: Gram diff + masked MSE accumulation ------------
// grid NSEG, block 256. Block i: row i cached in smem; thread j does dot.
// (CC == 256 == blockDim.x, so pic/pir fills exactly cover the row.)
__global__ void __launch_bounds__(256) k_gram() {
    __shared__ float pic[CC], pir[CC];
    __shared__ float red[8];
    const int i   = blockIdx.x;
    const int tid = threadIdx.x;
    const int warp = tid >> 5, lane = tid & 31;

    pic[tid] = g_pT_cur[(size_t)tid * NSEG + i];
    pir[tid] = g_pT_ref[(size_t)tid * NSEG + i];
    __syncthreads();

    const float vmi = g_vm[i];
    float local = 0.0f;
    if (tid < NSEG && vmi != 0.0f) {
        const float vmj = g_vm[tid];
        if (vmj != 0.0f) {
            float dc = 0.0f, dr = 0.0f;
#pragma unroll 8
            for (int c = 0; c < CC; c++) {
                dc += pic[c] * g_pT_cur[(size_t)c * NSEG + tid];
                dr += pir[c] * g_pT_ref[(size_t)c * NSEG + tid];
            }
            const float d = dc - dr;
            local = d * d;
        }
    }
#pragma unroll
    for (int off = 16; off; off >>= 1) local += __shfl_down_sync(0xffffffffu, local, off);
    if (lane == 0) red[warp] = local;
    __syncthreads();
    if (warp == 0) {
        float v = (lane < 8) ? red[lane] : 0.0f;
#pragma unroll
        for (int off = 4; off; off >>= 1) v += __shfl_down_sync(0xffffffffu, v, off);
        if (lane == 0 && v != 0.0f) atomicAdd(&g_sq, v);
    }
}

// ---------------- kernel 5: finalize -> d_out ------------------------------
__global__ void k_final(float* __restrict__ out) {
    float k = 0.0f;
    for (int i = threadIdx.x; i < NSEG; i += 32) k += g_vm[i];
#pragma unroll
    for (int off = 16; off; off >>= 1) k += __shfl_down_sync(0xffffffffu, k, off);
    if (threadIdx.x == 0)
        out[0] = (k > 0.0f) ? (g_sq / fmaxf(k * k, 1.0f)) : 0.0f;
}

// ---------------- launch ----------------------------------------------------
// Inputs are mapped by element count (unambiguous for this problem) so we are
// robust to metadata ordering / scalar-materialization details:
//   16777216 -> features (1st occurrence), features_old (2nd)
//   2752512  -> outputs_old
//   131072   -> labels
//   5376     -> prototypes (unused)
//   1        -> num_old_class (optional; kernel falls back to 16 if absent)
extern "C" void kernel_launch(void* const* d_in, const int* in_sizes, int n_in,
                              void* d_out, int out_size) {
    const float* features     = nullptr;
    const float* features_old = nullptr;
    const float* outputs_old  = nullptr;
    const int*   labels       = nullptr;
    const int*   num_old      = nullptr;

    for (int i = 0; i < n_in; i++) {
        const int sz = in_sizes[i];
        if (sz == BB * CC * HWP) {
            if (!features) features = (const float*)d_in[i];
            else if (!features_old) features_old = (const float*)d_in[i];
        } else if (sz == BB * CO * HWP) {
            outputs_old = (const float*)d_in[i];
        } else if (sz == BB * HWP) {
            labels = (const int*)d_in[i];
        } else if (sz == 1) {
            num_old = (const int*)d_in[i];
        }
        // sz == CO*CC (prototypes): unused by the forward pass
    }
    float* out = (float*)d_out;

    k_zero<<<1, 256>>>();
    k_pseudo<<<dim3(HWP / 256, BB), 256>>>(outputs_old, labels, num_old);
    k_segsum<<<dim3(CC, BB), 256>>>(features, features_old);
    k_norm<<<NSEG, 256>>>();
    k_gram<<<NSEG, 256>>>();
    k_final<<<1, 32>>>(out);
}

// round 15
// speedup vs baseline: 1.0687x; 1.0687x over previous
#include <cuda_runtime.h>
#include <cuda_bf16.h>
#include <math.h>

// Problem constants (fixed by setup_inputs)
#define BB   8
#define CC   256
#define HH   128
#define WW   128
#define HWP  (HH * WW)        // 16384 pixels per image
#define CO   21
#define NSEG (BB * CO)        // 168
#define EPSN 1e-12f

// ---------------- scratch (device globals; no allocation allowed) ----------
__device__ unsigned char g_pseudo[BB * HWP];        // 128 KB
__device__ float g_sum_cur[NSEG * CC];              // 172 KB
__device__ float g_sum_ref[NSEG * CC];
__device__ int   g_cnt[NSEG];
__device__ float g_sq;

// ---------------- kernel 0: zero accumulators ------------------------------
__global__ void k_zero() {
    int t = threadIdx.x;
    if (t < NSEG) g_cnt[t] = 0;
    if (t == 0)   g_sq = 0.0f;
}

// ---------------- kernel 1: pseudo labels + per-seg counts -----------------
// grid (HWP/256, BB), block 256   (unchanged — proven correct)
__global__ void __launch_bounds__(256) k_pseudo(const float* __restrict__ outputs_old,
                                                const int*   __restrict__ labels,
                                                const int*   __restrict__ num_old) {
    __shared__ int s_cnt[CO];
    const int b   = blockIdx.y;
    const int p   = blockIdx.x * 256 + threadIdx.x;
    const int no  = num_old ? num_old[0] : 16;
    if (threadIdx.x < CO) s_cnt[threadIdx.x] = 0;
    __syncthreads();

    const float* base = outputs_old + (size_t)b * CO * HWP + p;
    float best = base[0];
    int   bi   = 0;
#pragma unroll
    for (int ch = 1; ch < CO; ch++) {
        float v = base[(size_t)ch * HWP];
        if (v > best) { best = v; bi = ch; }   // strict > keeps first occurrence (jnp.argmax)
    }
    const int lab = labels[b * HWP + p];
    const int cls = (lab < no) ? bi : 0;
    g_pseudo[b * HWP + p] = (unsigned char)cls;
    atomicAdd(&s_cnt[cls], 1);
    __syncthreads();
    if (threadIdx.x < CO)
        atomicAdd(&g_cnt[b * CO + threadIdx.x], s_cnt[threadIdx.x]);
}

// ---------------- kernel 2: fused segment sums (dominant kernel) -----------
// grid (CC, BB), block 256. One block per (b,c).   (unchanged — proven correct)
__global__ void __launch_bounds__(256) k_segsum(const float* __restrict__ feat,
                                                const float* __restrict__ feat_old) {
    __shared__ float s_cur[CO * 256];   // 21504 B
    __shared__ float s_ref[CO * 256];   // 21504 B
    const int tid = threadIdx.x;
    const int c   = blockIdx.x;
    const int b   = blockIdx.y;

#pragma unroll
    for (int r = 0; r < CO; r++) { s_cur[r * 256 + tid] = 0.0f; s_ref[r * 256 + tid] = 0.0f; }
    __syncthreads();

    const float4* __restrict__ f4 = (const float4*)(feat     + ((size_t)(b * CC + c)) * HWP);
    const float4* __restrict__ g4 = (const float4*)(feat_old + ((size_t)(b * CC + c)) * HWP);
    const uchar4* __restrict__ p4 = (const uchar4*)(g_pseudo + (size_t)b * HWP);

#pragma unroll
    for (int k = 0; k < HWP / 4 / 256; k++) {     // 16 iterations
        const int idx = k * 256 + tid;
        const float4 fv = f4[idx];
        const float4 gv = g4[idx];
        const uchar4 pv = p4[idx];
        s_cur[pv.x * 256 + tid] += fv.x;
        s_cur[pv.y * 256 + tid] += fv.y;
        s_cur[pv.z * 256 + tid] += fv.z;
        s_cur[pv.w * 256 + tid] += fv.w;
        s_ref[pv.x * 256 + tid] += gv.x;
        s_ref[pv.y * 256 + tid] += gv.y;
        s_ref[pv.z * 256 + tid] += gv.z;
        s_ref[pv.w * 256 + tid] += gv.w;
    }
    __syncthreads();

    const int warp = tid >> 5, lane = tid & 31;
    for (int row = warp; row < 2 * CO; row += 8) {
        const float* sarr = (row < CO) ? s_cur : s_ref;
        const int r = (row < CO) ? row : row - CO;
        float v = 0.0f;
#pragma unroll
        for (int k = 0; k < 8; k++) v += sarr[r * 256 + lane + k * 32];
#pragma unroll
        for (int off = 16; off; off >>= 1) v += __shfl_down_sync(0xffffffffu, v, off);
        if (lane == 0) {
            float* dst = (row < CO) ? g_sum_cur : g_sum_ref;
            dst[(size_t)(b * CO + r) * CC + c] = v;
        }
    }
}

// ---------------- kernel 3: fused norm + Gram diff + MSE accumulation ------
// KEY IDENTITY: normalize(sum/cnt) == sum/|sum|  (cnt cancels under L2 norm),
// so cosine Grams come directly from raw sums: d(i,j) = S_i.S_j/(|S_i||S_j|).
// grid NSEG, block 256 (8 warps). Block i caches row i in smem; each warp
// handles j = warp, warp+8, ... with coalesced 32-lane row reads (L2-resident),
// computing dot AND |S_j|^2 from the same loads.
__global__ void __launch_bounds__(256) k_gram2() {
    __shared__ float sic[CC], sir[CC];
    __shared__ float redn[2][8];
    __shared__ float s_inv[2];          // 1 / max(|S_i|, eps)
    __shared__ float redacc[8];
    const int i    = blockIdx.x;
    const int tid  = threadIdx.x;
    const int warp = tid >> 5, lane = tid & 31;

    const float vc = g_sum_cur[(size_t)i * CC + tid];
    const float vr = g_sum_ref[(size_t)i * CC + tid];
    sic[tid] = vc; sir[tid] = vr;

    // block-reduce |S_i|^2 for both matrices
    float nc = vc * vc, nr = vr * vr;
#pragma unroll
    for (int off = 16; off; off >>= 1) {
        nc += __shfl_down_sync(0xffffffffu, nc, off);
        nr += __shfl_down_sync(0xffffffffu, nr, off);
    }
    if (lane == 0) { redn[0][warp] = nc; redn[1][warp] = nr; }
    __syncthreads();
    if (warp == 0) {
        float a  = (lane < 8) ? redn[0][lane] : 0.0f;
        float b2 = (lane < 8) ? redn[1][lane] : 0.0f;
#pragma unroll
        for (int off = 4; off; off >>= 1) {
            a  += __shfl_down_sync(0xffffffffu, a,  off);
            b2 += __shfl_down_sync(0xffffffffu, b2, off);
        }
        if (lane == 0) {
            s_inv[0] = 1.0f / fmaxf(sqrtf(a),  EPSN);
            s_inv[1] = 1.0f / fmaxf(sqrtf(b2), EPSN);
        }
    }
    __syncthreads();

    const bool valid_i = (g_cnt[i] > 0) && (i % CO != 0);
    float acc = 0.0f;
    if (valid_i) {
        const float inc = s_inv[0], inr = s_inv[1];
        for (int j = warp; j < NSEG; j += 8) {          // warp-uniform j
            if (!((g_cnt[j] > 0) && (j % CO != 0))) continue;  // warp-uniform branch
            const float* __restrict__ rc = g_sum_cur + (size_t)j * CC;
            const float* __restrict__ rr = g_sum_ref + (size_t)j * CC;
            float dc = 0.0f, dr = 0.0f, njc = 0.0f, njr = 0.0f;
#pragma unroll
            for (int k = 0; k < 8; k++) {
                const int c = k * 32 + lane;            // coalesced across lanes
                const float xc = rc[c], xr = rr[c];
                dc += xc * sic[c];  njc += xc * xc;
                dr += xr * sir[c];  njr += xr * xr;
            }
#pragma unroll
            for (int off = 16; off; off >>= 1) {
                dc  += __shfl_down_sync(0xffffffffu, dc,  off);
                dr  += __shfl_down_sync(0xffffffffu, dr,  off);
                njc += __shfl_down_sync(0xffffffffu, njc, off);
                njr += __shfl_down_sync(0xffffffffu, njr, off);
            }
            if (lane == 0) {
                const float dcur = dc * inc / fmaxf(sqrtf(njc), EPSN);
                const float dref = dr * inr / fmaxf(sqrtf(njr), EPSN);
                const float d = dcur - dref;
                acc += d * d;
            }
        }
    }
    // block-reduce acc (only lane 0 per warp holds data; reduce is cheap anyway)
#pragma unroll
    for (int off = 16; off; off >>= 1) acc += __shfl_down_sync(0xffffffffu, acc, off);
    if (lane == 0) redacc[warp] = acc;
    __syncthreads();
    if (warp == 0) {
        float v = (lane < 8) ? redacc[lane] : 0.0f;
#pragma unroll
        for (int off = 4; off; off >>= 1) v += __shfl_down_sync(0xffffffffu, v, off);
        if (lane == 0 && v != 0.0f) atomicAdd(&g_sq, v);
    }
}

// ---------------- kernel 4: finalize -> d_out ------------------------------
__global__ void k_final2(float* __restrict__ out) {
    float k = 0.0f;
    for (int i = threadIdx.x; i < NSEG; i += 32)
        k += ((g_cnt[i] > 0) && (i % CO != 0)) ? 1.0f : 0.0f;
#pragma unroll
    for (int off = 16; off; off >>= 1) k += __shfl_down_sync(0xffffffffu, k, off);
    if (threadIdx.x == 0)
        out[0] = (k > 0.0f) ? (g_sq / fmaxf(k * k, 1.0f)) : 0.0f;
}

// ---------------- launch ----------------------------------------------------
// Inputs mapped by element count (robust to metadata ordering):
//   16777216 -> features (1st), features_old (2nd); 2752512 -> outputs_old;
//   131072 -> labels; 5376 -> prototypes (unused); 1 -> num_old_class (opt.)
extern "C" void kernel_launch(void* const* d_in, const int* in_sizes, int n_in,
                              void* d_out, int out_size) {
    const float* features     = nullptr;
    const float* features_old = nullptr;
    const float* outputs_old  = nullptr;
    const int*   labels       = nullptr;
    const int*   num_old      = nullptr;

    for (int i = 0; i < n_in; i++) {
        const int sz = in_sizes[i];
        if (sz == BB * CC * HWP) {
            if (!features) features = (const float*)d_in[i];
            else if (!features_old) features_old = (const float*)d_in[i];
        } else if (sz == BB * CO * HWP) {
            outputs_old = (const float*)d_in[i];
        } else if (sz == BB * HWP) {
            labels = (const int*)d_in[i];
        } else if (sz == 1) {
            num_old = (const int*)d_in[i];
        }
    }
    float* out = (float*)d_out;

    k_zero<<<1, 256>>>();
    k_pseudo<<<dim3(HWP / 256, BB), 256>>>(outputs_old, labels, num_old);
    k_segsum<<<dim3(CC, BB), 256>>>(features, features_old);
    k_gram2<<<NSEG, 256>>>();
    k_final2<<<1, 32>>>(out);
}